// round 1
// baseline (speedup 1.0000x reference)
#include <cuda_runtime.h>

#define NUM_USERS 80000
#define NUM_ITEMS 40000
#define NUM_NODES 120000
#define DIM       64
#define NE        (NUM_NODES * DIM)     // 7,680,000
#define NE4       (NE / 4)              // 1,920,000
#define ALPHA     0.8f
#define MAX_EPATH 2000000
#define WEDGES    128                    // edges per warp

// ---------------- scratch (device globals; no dynamic allocation) ----------
__device__ __align__(256) float g_e[NE];       // current embedding e
__device__ __align__(256) float g_t[NE];       // scatter target (e_pos - a*e_neg) / path out
__device__ __align__(256) float g_acc[NE];     // running sum for mean
__device__ __align__(256) float g_softv[MAX_EPATH];
__device__ __align__(256) float g_rowsum[NUM_NODES];
__device__ __align__(256) float g_thetaw[8];

// ---------------- tiny softmax over theta (6 vals) -------------------------
__global__ void k_theta(const float* __restrict__ theta, float* __restrict__ tw, int n)
{
    float m = -1e30f;
    for (int k = 0; k < n; k++) m = fmaxf(m, theta[k]);
    float s = 0.f;
    float w[8];
    for (int k = 0; k < n; k++) { w[k] = expf(theta[k] - m); s += w[k]; }
    for (int k = 0; k < n; k++) tw[k] = w[k] / s;
}

// ---------------- zero a float4 region -------------------------------------
__global__ void k_zero4(float4* __restrict__ p, int n4)
{
    int i = blockIdx.x * blockDim.x + threadIdx.x;
    if (i < n4) p[i] = make_float4(0.f, 0.f, 0.f, 0.f);
}

// ---------------- path pass 1: exp(counts @ theta_w), row sums -------------
__global__ void k_path1(const int* __restrict__ p_row, const float* __restrict__ p_counts,
                        const float* __restrict__ tw, float* __restrict__ softv,
                        float* __restrict__ rowsum, int n)
{
    int i = blockIdx.x * blockDim.x + threadIdx.x;
    if (i >= n) return;
    float w0 = tw[0], w1 = tw[1], w2 = tw[2], w3 = tw[3], w4 = tw[4], w5 = tw[5];
    const float* c = p_counts + i * 6;
    float v = c[0] * w0;
    v = fmaf(c[1], w1, v);
    v = fmaf(c[2], w2, v);
    v = fmaf(c[3], w3, v);
    v = fmaf(c[4], w4, v);
    v = fmaf(c[5], w5, v);
    float ev = expf(v);
    softv[i] = ev;
    atomicAdd(&rowsum[p_row[i]], ev);
}

// ---------------- path pass 2: normalize ------------------------------------
__global__ void k_path2(const int* __restrict__ p_row, float* __restrict__ softv,
                        const float* __restrict__ rowsum, int n)
{
    int i = blockIdx.x * blockDim.x + threadIdx.x;
    if (i >= n) return;
    softv[i] = softv[i] / (rowsum[p_row[i]] + 1e-12f);
}

// ---------------- SpMM: y[row] += scale*val * x[col]  (rows sorted) --------
// warp handles WEDGES consecutive edges; metadata staged to smem (1 LDS.128
// broadcast/edge); each lane owns dims {2*lane, 2*lane+1}; register
// accumulation with atomic flush only on row change.
__global__ __launch_bounds__(256) void k_spmm(
    const int* __restrict__ rows, const int* __restrict__ cols,
    const float* __restrict__ vals, int n, float scale,
    const float* __restrict__ xa,   // nodes [0, NUM_USERS)
    const float* __restrict__ xb,   // nodes [NUM_USERS, NUM_NODES), indexed col-NUM_USERS
    float* __restrict__ y)
{
    __shared__ float4 meta[8][32];
    const int wslot = threadIdx.x >> 5;
    const int lane  = threadIdx.x & 31;
    const int wid   = blockIdx.x * 8 + wslot;
    const int base  = wid * WEDGES;
    if (base >= n) return;
    const int cnt = min(WEDGES, n - base);

    float acc0 = 0.f, acc1 = 0.f;
    int cur = -1;

    for (int t0 = 0; t0 < cnt; t0 += 32) {
        const int m = min(32, cnt - t0);
        int r = 0, c = 0; float v = 0.f;
        if (lane < m) {
            int i = base + t0 + lane;
            r = rows[i]; c = cols[i]; v = vals[i];
        }
        meta[wslot][lane] = make_float4(__int_as_float(r), __int_as_float(c), v * scale, 0.f);
        __syncwarp();
        #pragma unroll 4
        for (int j = 0; j < m; j++) {
            float4 md = meta[wslot][j];
            int   rj = __float_as_int(md.x);
            int   cj = __float_as_int(md.y);
            float f  = md.z;
            if (rj != cur) {                       // warp-uniform branch
                if (cur >= 0) {
                    float* p = y + cur * DIM + 2 * lane;
                    atomicAdd(p,     acc0);
                    atomicAdd(p + 1, acc1);
                }
                cur = rj; acc0 = 0.f; acc1 = 0.f;
            }
            const float* xs = (cj < NUM_USERS) ? (xa + cj * DIM)
                                               : (xb + (cj - NUM_USERS) * DIM);
            float2 xv = *(const float2*)(xs + 2 * lane);
            acc0 = fmaf(f, xv.x, acc0);
            acc1 = fmaf(f, xv.y, acc1);
        }
        __syncwarp();
    }
    if (cur >= 0) {
        float* p = y + cur * DIM + 2 * lane;
        atomicAdd(p,     acc0);
        atomicAdd(p + 1, acc1);
    }
}

// ---------------- init after path spmm: e = t; acc = t; t = 0 --------------
__global__ void k_init(float4* __restrict__ T, float4* __restrict__ E,
                       float4* __restrict__ A, int n4)
{
    int i = blockIdx.x * blockDim.x + threadIdx.x;
    if (i >= n4) return;
    float4 t = T[i];
    E[i] = t;
    A[i] = t;
    T[i] = make_float4(0.f, 0.f, 0.f, 0.f);
}

// ---------------- per-layer epilogue: e = t + a*e; acc += e; t = 0 ---------
__global__ void k_layer(float4* __restrict__ T, float4* __restrict__ E,
                        float4* __restrict__ A, int n4)
{
    int i = blockIdx.x * blockDim.x + threadIdx.x;
    if (i >= n4) return;
    float4 t = T[i];
    float4 e = E[i];
    e.x = fmaf(ALPHA, e.x, t.x);
    e.y = fmaf(ALPHA, e.y, t.y);
    e.z = fmaf(ALPHA, e.z, t.z);
    e.w = fmaf(ALPHA, e.w, t.w);
    E[i] = e;
    float4 a = A[i];
    a.x += e.x; a.y += e.y; a.z += e.z; a.w += e.w;
    A[i] = a;
    T[i] = make_float4(0.f, 0.f, 0.f, 0.f);
}

// ---------------- final: out = acc / 4 -------------------------------------
__global__ void k_out(const float4* __restrict__ A, float4* __restrict__ O, int n4)
{
    int i = blockIdx.x * blockDim.x + threadIdx.x;
    if (i >= n4) return;
    float4 a = A[i];
    a.x *= 0.25f; a.y *= 0.25f; a.z *= 0.25f; a.w *= 0.25f;
    O[i] = a;
}

// ---------------------------------------------------------------------------
static inline void launch_spmm(const int* r, const int* c, const float* v, int n,
                               float scale, const float* xa, const float* xb, float* y)
{
    int warps  = (n + WEDGES - 1) / WEDGES;
    int blocks = (warps + 7) / 8;
    k_spmm<<<blocks, 256>>>(r, c, v, n, scale, xa, xb, y);
}

extern "C" void kernel_launch(void* const* d_in, const int* in_sizes, int n_in,
                              void* d_out, int out_size)
{
    const float* user_emb = (const float*)d_in[0];
    const float* item_emb = (const float*)d_in[1];
    const float* theta    = (const float*)d_in[2];
    const int*   pos_row  = (const int*)d_in[3];
    const int*   pos_col  = (const int*)d_in[4];
    const float* pos_val  = (const float*)d_in[5];
    const int*   neg_row  = (const int*)d_in[6];
    const int*   neg_col  = (const int*)d_in[7];
    const float* neg_val  = (const float*)d_in[8];
    const int*   p_row    = (const int*)d_in[9];
    const int*   p_col    = (const int*)d_in[10];
    const float* p_counts = (const float*)d_in[11];

    const int n_pos  = in_sizes[3];
    const int n_neg  = in_sizes[6];
    int n_path = in_sizes[9];
    if (n_path > MAX_EPATH) n_path = MAX_EPATH;
    const int n_theta = in_sizes[2] < 8 ? in_sizes[2] : 8;

    float *pe, *pt, *pacc, *psv, *prs, *ptw;
    cudaGetSymbolAddress((void**)&pe,   g_e);
    cudaGetSymbolAddress((void**)&pt,   g_t);
    cudaGetSymbolAddress((void**)&pacc, g_acc);
    cudaGetSymbolAddress((void**)&psv,  g_softv);
    cudaGetSymbolAddress((void**)&prs,  g_rowsum);
    cudaGetSymbolAddress((void**)&ptw,  g_thetaw);

    const int TB = 256;
    const int rs4 = NUM_NODES / 4;

    // theta softmax
    k_theta<<<1, 1>>>(theta, ptw, n_theta);

    // zero rowsum + scatter target
    k_zero4<<<(rs4 + TB - 1) / TB, TB>>>((float4*)prs, rs4);
    k_zero4<<<(NE4 + TB - 1) / TB, TB>>>((float4*)pt, NE4);

    // path softmax normalization
    k_path1<<<(n_path + TB - 1) / TB, TB>>>(p_row, p_counts, ptw, psv, prs, n_path);
    k_path2<<<(n_path + TB - 1) / TB, TB>>>(p_row, psv, prs, n_path);

    // e0 = spmm(path, soft_v, [user_emb; item_emb])  -> g_t
    launch_spmm(p_row, p_col, psv, n_path, 1.0f, user_emb, item_emb, pt);

    // e = e0; acc = e0; t = 0
    k_init<<<(NE4 + TB - 1) / TB, TB>>>((float4*)pt, (float4*)pe, (float4*)pacc, NE4);

    // 3 propagation layers: t = spmm_pos(e) - a*spmm_neg(e); e = t + a*e; acc += e
    for (int l = 0; l < 3; l++) {
        launch_spmm(pos_row, pos_col, pos_val, n_pos,  1.0f,  pe, pe + NUM_USERS * DIM, pt);
        launch_spmm(neg_row, neg_col, neg_val, n_neg, -ALPHA, pe, pe + NUM_USERS * DIM, pt);
        k_layer<<<(NE4 + TB - 1) / TB, TB>>>((float4*)pt, (float4*)pe, (float4*)pacc, NE4);
    }

    // out = acc / 4   (users rows 0..79999, items rows 80000..119999)
    k_out<<<(NE4 + TB - 1) / TB, TB>>>((const float4*)pacc, (float4*)d_out, NE4);
}

// round 2
// speedup vs baseline: 1.1226x; 1.1226x over previous
#include <cuda_runtime.h>
#include <cuda_fp16.h>

#define NUM_USERS 80000
#define NUM_ITEMS 40000
#define NUM_NODES 120000
#define DIM       64
#define NE        (NUM_NODES * DIM)     // 7,680,000
#define NE4       (NE / 4)              // 1,920,000
#define ALPHA     0.8f
#define MAX_EPATH 2000000
#define WEDGES    128                    // edges per warp

// ---------------- scratch (device globals; zero-initialized .bss) ----------
__device__ __align__(256) float   g_t[NE];          // fp32 scatter target (invariant: zero at entry)
__device__ __align__(256) float   g_acc[NE];        // running sum for mean
__device__ __align__(256) __half2 g_eA[NE / 2];     // fp16 embedding ping
__device__ __align__(256) __half2 g_eB[NE / 2];     // fp16 embedding pong
__device__ __align__(256) float   g_softv[MAX_EPATH];
__device__ __align__(256) float   g_rowsum[NUM_NODES];
__device__ __align__(256) float   g_thetaw[8];

// ---------------- tiny softmax over theta -----------------------------------
__global__ void k_theta(const float* __restrict__ theta, float* __restrict__ tw, int n)
{
    float m = -1e30f;
    for (int k = 0; k < n; k++) m = fmaxf(m, theta[k]);
    float s = 0.f; float w[8];
    for (int k = 0; k < n; k++) { w[k] = expf(theta[k] - m); s += w[k]; }
    for (int k = 0; k < n; k++) tw[k] = w[k] / s;
}

__global__ void k_zero4(float4* __restrict__ p, int n4)
{
    int i = blockIdx.x * blockDim.x + threadIdx.x;
    if (i < n4) p[i] = make_float4(0.f, 0.f, 0.f, 0.f);
}

// ---------------- path pass: exp(counts @ theta_w), row sums ---------------
// p_counts rows are 24B (6 floats) -> stage a block's worth through smem with
// coalesced float4 loads, then each thread reads its own 6 from smem.
__global__ __launch_bounds__(256) void k_path1(
    const int* __restrict__ p_row, const float* __restrict__ p_counts,
    const float* __restrict__ tw, float* __restrict__ softv,
    float* __restrict__ rowsum, int n)
{
    __shared__ float sc[256 * 6];
    const int base = blockIdx.x * 256;
    const int m    = min(256, n - base);
    if (m == 256) {
        const float4* src = (const float4*)(p_counts + (size_t)base * 6);
        #pragma unroll
        for (int k = threadIdx.x; k < 384; k += 256)
            ((float4*)sc)[k] = src[k];
    } else {
        for (int k = threadIdx.x; k < m * 6; k += 256)
            sc[k] = p_counts[(size_t)base * 6 + k];
    }
    __syncthreads();
    const int i = base + threadIdx.x;
    if (threadIdx.x >= m) return;
    const float* c = sc + threadIdx.x * 6;
    float v = c[0] * tw[0];
    v = fmaf(c[1], tw[1], v);
    v = fmaf(c[2], tw[2], v);
    v = fmaf(c[3], tw[3], v);
    v = fmaf(c[4], tw[4], v);
    v = fmaf(c[5], tw[5], v);
    float ev = expf(v);
    softv[i] = ev;
    atomicAdd(&rowsum[p_row[i]], ev);
}

// ---------------- path SpMM (fp32 gather, split tables, fused softmax norm) -
// rows sorted; warp-register accumulation, atomic flush on row change.
__global__ __launch_bounds__(256) void k_spmm_path(
    const int* __restrict__ rows, const int* __restrict__ cols,
    const float* __restrict__ evals, const float* __restrict__ rowsum, int n,
    const float* __restrict__ xa, const float* __restrict__ xb,
    float* __restrict__ y)
{
    __shared__ float4 meta[8][32];
    const int wslot = threadIdx.x >> 5;
    const int lane  = threadIdx.x & 31;
    const int base  = (blockIdx.x * 8 + wslot) * WEDGES;
    if (base >= n) return;
    const int cnt = min(WEDGES, n - base);

    float acc0 = 0.f, acc1 = 0.f, inv = 0.f;
    int cur = -1;

    for (int t0 = 0; t0 < cnt; t0 += 32) {
        const int m = min(32, cnt - t0);
        int r = 0, c = 0; float v = 0.f;
        if (lane < m) {
            int i = base + t0 + lane;
            r = rows[i]; c = cols[i]; v = evals[i];
        }
        meta[wslot][lane] = make_float4(__int_as_float(r), __int_as_float(c), v, 0.f);
        __syncwarp();
        #pragma unroll 4
        for (int j = 0; j < m; j++) {
            float4 md = meta[wslot][j];
            int   rj = __float_as_int(md.x);
            int   cj = __float_as_int(md.y);
            if (rj != cur) {
                if (cur >= 0) {
                    float* p = y + cur * DIM + 2 * lane;
                    atomicAdd(p,     acc0);
                    atomicAdd(p + 1, acc1);
                }
                cur = rj; acc0 = 0.f; acc1 = 0.f;
                inv = 1.f / (rowsum[rj] + 1e-12f);
            }
            float f = md.z * inv;
            const float* xs = (cj < NUM_USERS) ? (xa + cj * DIM)
                                               : (xb + (cj - NUM_USERS) * DIM);
            float2 xv = *(const float2*)(xs + 2 * lane);
            acc0 = fmaf(f, xv.x, acc0);
            acc1 = fmaf(f, xv.y, acc1);
        }
        __syncwarp();
    }
    if (cur >= 0) {
        float* p = y + cur * DIM + 2 * lane;
        atomicAdd(p,     acc0);
        atomicAdd(p + 1, acc1);
    }
}

// ---------------- layer SpMM (fp16 gather, single contiguous table) --------
__global__ __launch_bounds__(256) void k_spmm_h(
    const int* __restrict__ rows, const int* __restrict__ cols,
    const float* __restrict__ vals, int n, float scale,
    const __half2* __restrict__ x, float* __restrict__ y)
{
    __shared__ float4 meta[8][32];
    const int wslot = threadIdx.x >> 5;
    const int lane  = threadIdx.x & 31;
    const int base  = (blockIdx.x * 8 + wslot) * WEDGES;
    if (base >= n) return;
    const int cnt = min(WEDGES, n - base);

    float acc0 = 0.f, acc1 = 0.f;
    int cur = -1;

    for (int t0 = 0; t0 < cnt; t0 += 32) {
        const int m = min(32, cnt - t0);
        int r = 0, c = 0; float v = 0.f;
        if (lane < m) {
            int i = base + t0 + lane;
            r = rows[i]; c = cols[i]; v = vals[i];
        }
        meta[wslot][lane] = make_float4(__int_as_float(r), __int_as_float(c), v * scale, 0.f);
        __syncwarp();
        #pragma unroll 4
        for (int j = 0; j < m; j++) {
            float4 md = meta[wslot][j];
            int   rj = __float_as_int(md.x);
            int   cj = __float_as_int(md.y);
            float f  = md.z;
            if (rj != cur) {
                if (cur >= 0) {
                    float* p = y + cur * DIM + 2 * lane;
                    atomicAdd(p,     acc0);
                    atomicAdd(p + 1, acc1);
                }
                cur = rj; acc0 = 0.f; acc1 = 0.f;
            }
            float2 xv = __half22float2(x[cj * 32 + lane]);   // 128B row, 1 L2 line
            acc0 = fmaf(f, xv.x, acc0);
            acc1 = fmaf(f, xv.y, acc1);
        }
        __syncwarp();
    }
    if (cur >= 0) {
        float* p = y + cur * DIM + 2 * lane;
        atomicAdd(p,     acc0);
        atomicAdd(p + 1, acc1);
    }
}

// ---------------- e0 epilogue: A = half(t); acc = t; t = 0 ------------------
__global__ void k_init(float4* __restrict__ T, __half2* __restrict__ A,
                       float4* __restrict__ ACC, int n4)
{
    int i = blockIdx.x * blockDim.x + threadIdx.x;
    if (i >= n4) return;
    float4 t = T[i];
    A[2 * i]     = __floats2half2_rn(t.x, t.y);
    A[2 * i + 1] = __floats2half2_rn(t.z, t.w);
    ACC[i] = t;
    T[i] = make_float4(0.f, 0.f, 0.f, 0.f);
}

// ---------------- layer epilogue: e = t + a*eold; Enew = half(e); acc += e; t=0
__global__ void k_layer(float4* __restrict__ T, const __half2* __restrict__ Eold,
                        __half2* __restrict__ Enew, float4* __restrict__ ACC, int n4)
{
    int i = blockIdx.x * blockDim.x + threadIdx.x;
    if (i >= n4) return;
    float4 t = T[i];
    float2 e01 = __half22float2(Eold[2 * i]);
    float2 e23 = __half22float2(Eold[2 * i + 1]);
    float ex = fmaf(ALPHA, e01.x, t.x);
    float ey = fmaf(ALPHA, e01.y, t.y);
    float ez = fmaf(ALPHA, e23.x, t.z);
    float ew = fmaf(ALPHA, e23.y, t.w);
    Enew[2 * i]     = __floats2half2_rn(ex, ey);
    Enew[2 * i + 1] = __floats2half2_rn(ez, ew);
    float4 a = ACC[i];
    a.x += ex; a.y += ey; a.z += ez; a.w += ew;
    ACC[i] = a;
    T[i] = make_float4(0.f, 0.f, 0.f, 0.f);
}

// ---------------- final: out = (acc + t + a*eold)/4; t = 0 ------------------
__global__ void k_final(float4* __restrict__ T, const __half2* __restrict__ Eold,
                        const float4* __restrict__ ACC, float4* __restrict__ O, int n4)
{
    int i = blockIdx.x * blockDim.x + threadIdx.x;
    if (i >= n4) return;
    float4 t = T[i];
    float2 e01 = __half22float2(Eold[2 * i]);
    float2 e23 = __half22float2(Eold[2 * i + 1]);
    float4 a = ACC[i];
    float4 o;
    o.x = (a.x + fmaf(ALPHA, e01.x, t.x)) * 0.25f;
    o.y = (a.y + fmaf(ALPHA, e01.y, t.y)) * 0.25f;
    o.z = (a.z + fmaf(ALPHA, e23.x, t.z)) * 0.25f;
    o.w = (a.w + fmaf(ALPHA, e23.y, t.w)) * 0.25f;
    O[i] = o;
    T[i] = make_float4(0.f, 0.f, 0.f, 0.f);   // keep zero-at-entry invariant
}

// ---------------------------------------------------------------------------
extern "C" void kernel_launch(void* const* d_in, const int* in_sizes, int n_in,
                              void* d_out, int out_size)
{
    const float* user_emb = (const float*)d_in[0];
    const float* item_emb = (const float*)d_in[1];
    const float* theta    = (const float*)d_in[2];
    const int*   pos_row  = (const int*)d_in[3];
    const int*   pos_col  = (const int*)d_in[4];
    const float* pos_val  = (const float*)d_in[5];
    const int*   neg_row  = (const int*)d_in[6];
    const int*   neg_col  = (const int*)d_in[7];
    const float* neg_val  = (const float*)d_in[8];
    const int*   p_row    = (const int*)d_in[9];
    const int*   p_col    = (const int*)d_in[10];
    const float* p_counts = (const float*)d_in[11];

    const int n_pos  = in_sizes[3];
    const int n_neg  = in_sizes[6];
    int n_path = in_sizes[9];
    if (n_path > MAX_EPATH) n_path = MAX_EPATH;
    const int n_theta = in_sizes[2] < 8 ? in_sizes[2] : 8;

    float *pt, *pacc, *psv, *prs, *ptw;
    __half2 *pA, *pB;
    cudaGetSymbolAddress((void**)&pt,   g_t);
    cudaGetSymbolAddress((void**)&pacc, g_acc);
    cudaGetSymbolAddress((void**)&pA,   g_eA);
    cudaGetSymbolAddress((void**)&pB,   g_eB);
    cudaGetSymbolAddress((void**)&psv,  g_softv);
    cudaGetSymbolAddress((void**)&prs,  g_rowsum);
    cudaGetSymbolAddress((void**)&ptw,  g_thetaw);

    const int TB = 256;

    // theta softmax + rowsum zero
    k_theta<<<1, 1>>>(theta, ptw, n_theta);
    k_zero4<<<(NUM_NODES / 4 + TB - 1) / TB, TB>>>((float4*)prs, NUM_NODES / 4);

    // path edge weights (exp + rowsums); normalization folded into spmm
    k_path1<<<(n_path + TB - 1) / TB, TB>>>(p_row, p_counts, ptw, psv, prs, n_path);

    // e0 = spmm(path, softv/rowsum, [user_emb; item_emb]) -> t   (t zero at entry)
    {
        int warps  = (n_path + WEDGES - 1) / WEDGES;
        k_spmm_path<<<(warps + 7) / 8, TB>>>(p_row, p_col, psv, prs, n_path,
                                             user_emb, item_emb, pt);
    }

    // A = half(e0); acc = e0; t = 0
    k_init<<<(NE4 + TB - 1) / TB, TB>>>((float4*)pt, pA, (float4*)pacc, NE4);

    const int wpos = (n_pos + WEDGES - 1) / WEDGES;
    const int wneg = (n_neg + WEDGES - 1) / WEDGES;

    // layer 1: gather A -> t; e1 -> B
    k_spmm_h<<<(wpos + 7) / 8, TB>>>(pos_row, pos_col, pos_val, n_pos,  1.0f,  pA, pt);
    k_spmm_h<<<(wneg + 7) / 8, TB>>>(neg_row, neg_col, neg_val, n_neg, -ALPHA, pA, pt);
    k_layer<<<(NE4 + TB - 1) / TB, TB>>>((float4*)pt, pA, pB, (float4*)pacc, NE4);

    // layer 2: gather B -> t; e2 -> A
    k_spmm_h<<<(wpos + 7) / 8, TB>>>(pos_row, pos_col, pos_val, n_pos,  1.0f,  pB, pt);
    k_spmm_h<<<(wneg + 7) / 8, TB>>>(neg_row, neg_col, neg_val, n_neg, -ALPHA, pB, pt);
    k_layer<<<(NE4 + TB - 1) / TB, TB>>>((float4*)pt, pB, pA, (float4*)pacc, NE4);

    // layer 3: gather A -> t; fused final output
    k_spmm_h<<<(wpos + 7) / 8, TB>>>(pos_row, pos_col, pos_val, n_pos,  1.0f,  pA, pt);
    k_spmm_h<<<(wneg + 7) / 8, TB>>>(neg_row, neg_col, neg_val, n_neg, -ALPHA, pA, pt);
    k_final<<<(NE4 + TB - 1) / TB, TB>>>((float4*)pt, pA, (float4*)pacc,
                                         (float4*)d_out, NE4);
}

// round 3
// speedup vs baseline: 1.1914x; 1.0612x over previous
#include <cuda_runtime.h>
#include <cuda_fp16.h>

#define NUM_USERS 80000
#define NUM_ITEMS 40000
#define NUM_NODES 120000
#define DIM       64
#define NE        (NUM_NODES * DIM)     // 7,680,000
#define NE4       (NE / 4)              // 1,920,000
#define ALPHA     0.8f
#define MAX_EPATH 2000000
#define WEDGES    128                    // edges per warp
#define QE        (WEDGES / 4)           // edges per quarter-warp

// ---------------- scratch (device globals; zero-initialized .bss) ----------
__device__ __align__(256) float   g_t[NE];        // fp32 scatter target (zero at entry, restored at exit)
__device__ __align__(256) __half2 g_h0[NE / 2];   // e0 (fp16)
__device__ __align__(256) __half2 g_h1[NE / 2];   // e1 (fp16)
__device__ __align__(256) __half2 g_h2[NE / 2];   // e2 (fp16)
__device__ __align__(256) float   g_softv[MAX_EPATH];
__device__ __align__(256) float   g_rowsum[NUM_NODES];
__device__ __align__(256) float   g_thetaw[8];

// ---------------- tiny softmax over theta -----------------------------------
__global__ void k_theta(const float* __restrict__ theta, float* __restrict__ tw, int n)
{
    float m = -1e30f;
    for (int k = 0; k < n; k++) m = fmaxf(m, theta[k]);
    float s = 0.f; float w[8];
    for (int k = 0; k < n; k++) { w[k] = expf(theta[k] - m); s += w[k]; }
    for (int k = 0; k < n; k++) tw[k] = w[k] / s;
}

__global__ void k_zero4(float4* __restrict__ p, int n4)
{
    int i = blockIdx.x * blockDim.x + threadIdx.x;
    if (i < n4) p[i] = make_float4(0.f, 0.f, 0.f, 0.f);
}

// ---------------- path pass: exp(counts @ theta_w), row sums ---------------
__global__ __launch_bounds__(256) void k_path1(
    const int* __restrict__ p_row, const float* __restrict__ p_counts,
    const float* __restrict__ tw, float* __restrict__ softv,
    float* __restrict__ rowsum, int n)
{
    __shared__ float sc[256 * 6];
    const int base = blockIdx.x * 256;
    const int m    = min(256, n - base);
    if (m == 256) {
        const float4* src = (const float4*)(p_counts + (size_t)base * 6);
        #pragma unroll
        for (int k = threadIdx.x; k < 384; k += 256)
            ((float4*)sc)[k] = src[k];
    } else {
        for (int k = threadIdx.x; k < m * 6; k += 256)
            sc[k] = p_counts[(size_t)base * 6 + k];
    }
    __syncthreads();
    const int i = base + threadIdx.x;
    if (threadIdx.x >= m) return;
    const float* c = sc + threadIdx.x * 6;
    float v = c[0] * tw[0];
    v = fmaf(c[1], tw[1], v);
    v = fmaf(c[2], tw[2], v);
    v = fmaf(c[3], tw[3], v);
    v = fmaf(c[4], tw[4], v);
    v = fmaf(c[5], tw[5], v);
    float ev = expf(v);
    softv[i] = ev;
    atomicAdd(&rowsum[p_row[i]], ev);
}

// ============================================================================
// Quarter-warp SpMM bodies. Warp = 4 quarters; quarter = 8 lanes; each quarter
// processes its own contiguous edge sub-chunk; each lane owns 8 dims.
// Rows sorted -> register accumulation, atomic flush only on row change.
// ============================================================================

// fp16 gather variant (layer SpMMs). x is the fp16 table viewed as uint4 rows
// of 8 entries (8 halves per lane).
__device__ __forceinline__ void spmm_chunk_h(
    const int* __restrict__ rows, const int* __restrict__ cols,
    const float* __restrict__ vals, int base, int cnt, float scale,
    const uint4* __restrict__ x, float* __restrict__ y,
    float4* __restrict__ meta, int lane)
{
    for (int i = lane; i < cnt; i += 32) {
        int gi = base + i;
        meta[i] = make_float4(__int_as_float(rows[gi]), __int_as_float(cols[gi]),
                              vals[gi] * scale, 0.f);
    }
    __syncwarp();
    const int q = lane >> 3, ql = lane & 7;
    const int qbeg = q * QE;
    const int qend = min(qbeg + QE, cnt);

    float acc[8];
    #pragma unroll
    for (int k = 0; k < 8; k++) acc[k] = 0.f;
    int cur = -1;

    for (int j = qbeg; j < qend; j++) {
        float4 md = meta[j];
        int   rj = __float_as_int(md.x);
        int   cj = __float_as_int(md.y);
        float f  = md.z;
        if (rj != cur) {
            if (cur >= 0) {
                float* p = y + cur * DIM + ql * 8;
                #pragma unroll
                for (int k = 0; k < 8; k++) atomicAdd(p + k, acc[k]);
            }
            cur = rj;
            #pragma unroll
            for (int k = 0; k < 8; k++) acc[k] = 0.f;
        }
        uint4 hv = x[cj * 8 + ql];                 // 16B = 8 halves; 128B/row/quarter
        float2 p0 = __half22float2(*(const __half2*)&hv.x);
        float2 p1 = __half22float2(*(const __half2*)&hv.y);
        float2 p2 = __half22float2(*(const __half2*)&hv.z);
        float2 p3 = __half22float2(*(const __half2*)&hv.w);
        acc[0] = fmaf(f, p0.x, acc[0]); acc[1] = fmaf(f, p0.y, acc[1]);
        acc[2] = fmaf(f, p1.x, acc[2]); acc[3] = fmaf(f, p1.y, acc[3]);
        acc[4] = fmaf(f, p2.x, acc[4]); acc[5] = fmaf(f, p2.y, acc[5]);
        acc[6] = fmaf(f, p3.x, acc[6]); acc[7] = fmaf(f, p3.y, acc[7]);
    }
    if (cur >= 0) {
        float* p = y + cur * DIM + ql * 8;
        #pragma unroll
        for (int k = 0; k < 8; k++) atomicAdd(p + k, acc[k]);
    }
}

// ---------------- fused pos+neg layer SpMM ----------------------------------
__global__ __launch_bounds__(256) void k_spmm_dual(
    const int* __restrict__ prow, const int* __restrict__ pcol,
    const float* __restrict__ pval, int npos, int pos_blocks,
    const int* __restrict__ nrow, const int* __restrict__ ncol,
    const float* __restrict__ nval, int nneg,
    const uint4* __restrict__ x, float* __restrict__ y)
{
    __shared__ float4 meta[8][WEDGES];
    const int wslot = threadIdx.x >> 5;
    const int lane  = threadIdx.x & 31;

    const bool isneg = (blockIdx.x >= pos_blocks);
    const int  bid   = isneg ? (blockIdx.x - pos_blocks) : blockIdx.x;
    const int* rows  = isneg ? nrow : prow;
    const int* cols  = isneg ? ncol : pcol;
    const float* vals = isneg ? nval : pval;
    const int  n     = isneg ? nneg : npos;
    const float scale = isneg ? -ALPHA : 1.0f;

    const int base = (bid * 8 + wslot) * WEDGES;
    if (base >= n) return;
    const int cnt = min(WEDGES, n - base);
    spmm_chunk_h(rows, cols, vals, base, cnt, scale, x, y, meta[wslot], lane);
}

// ---------------- path SpMM (fp32 gather, split tables, fused softmax norm) -
__global__ __launch_bounds__(256) void k_spmm_path(
    const int* __restrict__ rows, const int* __restrict__ cols,
    const float* __restrict__ evals, const float* __restrict__ rowsum, int n,
    const float* __restrict__ xa, const float* __restrict__ xb,
    float* __restrict__ y)
{
    __shared__ float4 meta[8][WEDGES];
    const int wslot = threadIdx.x >> 5;
    const int lane  = threadIdx.x & 31;
    const int base  = (blockIdx.x * 8 + wslot) * WEDGES;
    if (base >= n) return;
    const int cnt = min(WEDGES, n - base);

    float4* m = meta[wslot];
    for (int i = lane; i < cnt; i += 32) {
        int gi = base + i;
        m[i] = make_float4(__int_as_float(rows[gi]), __int_as_float(cols[gi]),
                           evals[gi], 0.f);
    }
    __syncwarp();
    const int q = lane >> 3, ql = lane & 7;
    const int qbeg = q * QE;
    const int qend = min(qbeg + QE, cnt);

    float acc[8];
    #pragma unroll
    for (int k = 0; k < 8; k++) acc[k] = 0.f;
    int cur = -1; float inv = 1.f;

    for (int j = qbeg; j < qend; j++) {
        float4 md = m[j];
        int   rj = __float_as_int(md.x);
        int   cj = __float_as_int(md.y);
        if (rj != cur) {
            if (cur >= 0) {
                float* p = y + cur * DIM + ql * 8;
                #pragma unroll
                for (int k = 0; k < 8; k++) atomicAdd(p + k, acc[k]);
            }
            cur = rj;
            #pragma unroll
            for (int k = 0; k < 8; k++) acc[k] = 0.f;
            inv = 1.f / (rowsum[rj] + 1e-12f);
        }
        float f = md.z * inv;
        const float* xs = (cj < NUM_USERS) ? (xa + cj * DIM)
                                           : (xb + (cj - NUM_USERS) * DIM);
        float4 v0 = *(const float4*)(xs + ql * 8);
        float4 v1 = *(const float4*)(xs + ql * 8 + 4);
        acc[0] = fmaf(f, v0.x, acc[0]); acc[1] = fmaf(f, v0.y, acc[1]);
        acc[2] = fmaf(f, v0.z, acc[2]); acc[3] = fmaf(f, v0.w, acc[3]);
        acc[4] = fmaf(f, v1.x, acc[4]); acc[5] = fmaf(f, v1.y, acc[5]);
        acc[6] = fmaf(f, v1.z, acc[6]); acc[7] = fmaf(f, v1.w, acc[7]);
    }
    if (cur >= 0) {
        float* p = y + cur * DIM + ql * 8;
        #pragma unroll
        for (int k = 0; k < 8; k++) atomicAdd(p + k, acc[k]);
    }
}

// ---------------- e0 epilogue: H0 = half(t); t = 0 ---------------------------
__global__ void k_init(float4* __restrict__ T, __half2* __restrict__ H, int n4)
{
    int i = blockIdx.x * blockDim.x + threadIdx.x;
    if (i >= n4) return;
    float4 t = T[i];
    H[2 * i]     = __floats2half2_rn(t.x, t.y);
    H[2 * i + 1] = __floats2half2_rn(t.z, t.w);
    T[i] = make_float4(0.f, 0.f, 0.f, 0.f);
}

// ---------------- layer epilogue: Hnew = half(t + a*Hold); t = 0 -------------
__global__ void k_layer(float4* __restrict__ T, const __half2* __restrict__ Hold,
                        __half2* __restrict__ Hnew, int n4)
{
    int i = blockIdx.x * blockDim.x + threadIdx.x;
    if (i >= n4) return;
    float4 t = T[i];
    float2 e01 = __half22float2(Hold[2 * i]);
    float2 e23 = __half22float2(Hold[2 * i + 1]);
    Hnew[2 * i]     = __floats2half2_rn(fmaf(ALPHA, e01.x, t.x), fmaf(ALPHA, e01.y, t.y));
    Hnew[2 * i + 1] = __floats2half2_rn(fmaf(ALPHA, e23.x, t.z), fmaf(ALPHA, e23.y, t.w));
    T[i] = make_float4(0.f, 0.f, 0.f, 0.f);
}

// ---------------- final: out = (H0 + H1 + H2 + (t + a*H2))/4; t = 0 ----------
__global__ void k_final(float4* __restrict__ T,
                        const __half2* __restrict__ H0,
                        const __half2* __restrict__ H1,
                        const __half2* __restrict__ H2,
                        float4* __restrict__ O, int n4)
{
    int i = blockIdx.x * blockDim.x + threadIdx.x;
    if (i >= n4) return;
    float4 t = T[i];
    float2 a01 = __half22float2(H0[2 * i]);
    float2 a23 = __half22float2(H0[2 * i + 1]);
    float2 b01 = __half22float2(H1[2 * i]);
    float2 b23 = __half22float2(H1[2 * i + 1]);
    float2 c01 = __half22float2(H2[2 * i]);
    float2 c23 = __half22float2(H2[2 * i + 1]);
    float4 o;
    o.x = (a01.x + b01.x + c01.x + fmaf(ALPHA, c01.x, t.x)) * 0.25f;
    o.y = (a01.y + b01.y + c01.y + fmaf(ALPHA, c01.y, t.y)) * 0.25f;
    o.z = (a23.x + b23.x + c23.x + fmaf(ALPHA, c23.x, t.z)) * 0.25f;
    o.w = (a23.y + b23.y + c23.y + fmaf(ALPHA, c23.y, t.w)) * 0.25f;
    O[i] = o;
    T[i] = make_float4(0.f, 0.f, 0.f, 0.f);   // keep zero-at-entry invariant
}

// ---------------------------------------------------------------------------
extern "C" void kernel_launch(void* const* d_in, const int* in_sizes, int n_in,
                              void* d_out, int out_size)
{
    const float* user_emb = (const float*)d_in[0];
    const float* item_emb = (const float*)d_in[1];
    const float* theta    = (const float*)d_in[2];
    const int*   pos_row  = (const int*)d_in[3];
    const int*   pos_col  = (const int*)d_in[4];
    const float* pos_val  = (const float*)d_in[5];
    const int*   neg_row  = (const int*)d_in[6];
    const int*   neg_col  = (const int*)d_in[7];
    const float* neg_val  = (const float*)d_in[8];
    const int*   p_row    = (const int*)d_in[9];
    const int*   p_col    = (const int*)d_in[10];
    const float* p_counts = (const float*)d_in[11];

    const int n_pos  = in_sizes[3];
    const int n_neg  = in_sizes[6];
    int n_path = in_sizes[9];
    if (n_path > MAX_EPATH) n_path = MAX_EPATH;
    const int n_theta = in_sizes[2] < 8 ? in_sizes[2] : 8;

    float *pt, *psv, *prs, *ptw;
    __half2 *h0, *h1, *h2;
    cudaGetSymbolAddress((void**)&pt,  g_t);
    cudaGetSymbolAddress((void**)&h0,  g_h0);
    cudaGetSymbolAddress((void**)&h1,  g_h1);
    cudaGetSymbolAddress((void**)&h2,  g_h2);
    cudaGetSymbolAddress((void**)&psv, g_softv);
    cudaGetSymbolAddress((void**)&prs, g_rowsum);
    cudaGetSymbolAddress((void**)&ptw, g_thetaw);

    const int TB = 256;

    // theta softmax + rowsum zero
    k_theta<<<1, 1>>>(theta, ptw, n_theta);
    k_zero4<<<(NUM_NODES / 4 + TB - 1) / TB, TB>>>((float4*)prs, NUM_NODES / 4);

    // path edge weights (exp + rowsums); normalization folded into spmm
    k_path1<<<(n_path + TB - 1) / TB, TB>>>(p_row, p_counts, ptw, psv, prs, n_path);

    // e0 = spmm(path, softv/rowsum, [user_emb; item_emb]) -> t
    {
        int warps = (n_path + WEDGES - 1) / WEDGES;
        k_spmm_path<<<(warps + 7) / 8, TB>>>(p_row, p_col, psv, prs, n_path,
                                             user_emb, item_emb, pt);
    }

    // H0 = half(e0); t = 0
    k_init<<<(NE4 + TB - 1) / TB, TB>>>((float4*)pt, h0, NE4);

    const int pos_blocks = ((n_pos + WEDGES - 1) / WEDGES + 7) / 8;
    const int neg_blocks = ((n_neg + WEDGES - 1) / WEDGES + 7) / 8;
    const int dual_grid  = pos_blocks + neg_blocks;

    // layer 1
    k_spmm_dual<<<dual_grid, TB>>>(pos_row, pos_col, pos_val, n_pos, pos_blocks,
                                   neg_row, neg_col, neg_val, n_neg,
                                   (const uint4*)h0, pt);
    k_layer<<<(NE4 + TB - 1) / TB, TB>>>((float4*)pt, h0, h1, NE4);

    // layer 2
    k_spmm_dual<<<dual_grid, TB>>>(pos_row, pos_col, pos_val, n_pos, pos_blocks,
                                   neg_row, neg_col, neg_val, n_neg,
                                   (const uint4*)h1, pt);
    k_layer<<<(NE4 + TB - 1) / TB, TB>>>((float4*)pt, h1, h2, NE4);

    // layer 3 + fused final mean
    k_spmm_dual<<<dual_grid, TB>>>(pos_row, pos_col, pos_val, n_pos, pos_blocks,
                                   neg_row, neg_col, neg_val, n_neg,
                                   (const uint4*)h2, pt);
    k_final<<<(NE4 + TB - 1) / TB, TB>>>((float4*)pt, h0, h1, h2,
                                         (float4*)d_out, NE4);
}

// round 4
// speedup vs baseline: 1.9180x; 1.6099x over previous
#include <cuda_runtime.h>
#include <cuda_fp16.h>

#define NUM_USERS 80000
#define NUM_ITEMS 40000
#define NUM_NODES 120000
#define DIM       64
#define NE        (NUM_NODES * DIM)     // 7,680,000
#define NE4       (NE / 4)              // 1,920,000
#define NU4       (NUM_USERS * DIM / 4) // 1,280,000
#define ALPHA     0.8f
#define MAX_EPATH 2000000
#define WEDGES    128                    // edges per warp
#define QE        (WEDGES / 4)           // edges per quarter-warp

// ---------------- scratch (device globals; zero-initialized .bss) ----------
__device__ __align__(256) float   g_t[NE];        // fp32 scatter target (zero at entry, restored at exit)
__device__ __align__(256) __half2 g_hin[NE / 2];  // fp16 copy of [user_emb; item_emb]
__device__ __align__(256) __half2 g_h0[NE / 2];   // e0 (fp16)
__device__ __align__(256) __half2 g_h1[NE / 2];   // e1 (fp16)
__device__ __align__(256) __half2 g_h2[NE / 2];   // e2 (fp16)
__device__ __align__(256) float   g_softv[MAX_EPATH];
__device__ __align__(256) float   g_rowsum[NUM_NODES];
__device__ __align__(256) float   g_thetaw[8];

// ---------------- tiny softmax over theta -----------------------------------
__global__ void k_theta(const float* __restrict__ theta, float* __restrict__ tw, int n)
{
    float m = -1e30f;
    for (int k = 0; k < n; k++) m = fmaxf(m, theta[k]);
    float s = 0.f; float w[8];
    for (int k = 0; k < n; k++) { w[k] = expf(theta[k] - m); s += w[k]; }
    for (int k = 0; k < n; k++) tw[k] = w[k] / s;
}

__global__ void k_zero4(float4* __restrict__ p, int n4)
{
    int i = blockIdx.x * blockDim.x + threadIdx.x;
    if (i < n4) p[i] = make_float4(0.f, 0.f, 0.f, 0.f);
}

// ---------------- convert [user_emb; item_emb] -> fp16 table ----------------
__global__ void k_cvt(const float4* __restrict__ U, const float4* __restrict__ I,
                      __half2* __restrict__ H, int n4)
{
    int i = blockIdx.x * blockDim.x + threadIdx.x;
    if (i >= n4) return;
    float4 v = (i < NU4) ? U[i] : I[i - NU4];
    H[2 * i]     = __floats2half2_rn(v.x, v.y);
    H[2 * i + 1] = __floats2half2_rn(v.z, v.w);
}

// ---------------- path pass: exp(counts @ theta_w), row sums ---------------
__global__ __launch_bounds__(256) void k_path1(
    const int* __restrict__ p_row, const float* __restrict__ p_counts,
    const float* __restrict__ tw, float* __restrict__ softv,
    float* __restrict__ rowsum, int n)
{
    __shared__ float sc[256 * 6];
    const int base = blockIdx.x * 256;
    const int m    = min(256, n - base);
    if (m == 256) {
        const float4* src = (const float4*)(p_counts + (size_t)base * 6);
        #pragma unroll
        for (int k = threadIdx.x; k < 384; k += 256)
            ((float4*)sc)[k] = src[k];
    } else {
        for (int k = threadIdx.x; k < m * 6; k += 256)
            sc[k] = p_counts[(size_t)base * 6 + k];
    }
    __syncthreads();
    const int i = base + threadIdx.x;
    if (threadIdx.x >= m) return;
    const float* c = sc + threadIdx.x * 6;
    float v = c[0] * tw[0];
    v = fmaf(c[1], tw[1], v);
    v = fmaf(c[2], tw[2], v);
    v = fmaf(c[3], tw[3], v);
    v = fmaf(c[4], tw[4], v);
    v = fmaf(c[5], tw[5], v);
    float ev = expf(v);
    softv[i] = ev;
    atomicAdd(&rowsum[p_row[i]], ev);
}

// ---------------- vector reduction flush (2 instrs instead of 8) -----------
__device__ __forceinline__ void flushv4(float* __restrict__ y, int row, int ql,
                                        const float* acc)
{
    float* p = y + row * DIM + ql * 8;
    asm volatile("red.global.add.v4.f32 [%0], {%1,%2,%3,%4};"
                 :: "l"(p), "f"(acc[0]), "f"(acc[1]), "f"(acc[2]), "f"(acc[3])
                 : "memory");
    asm volatile("red.global.add.v4.f32 [%0], {%1,%2,%3,%4};"
                 :: "l"(p + 4), "f"(acc[4]), "f"(acc[5]), "f"(acc[6]), "f"(acc[7])
                 : "memory");
}

// ============================================================================
// Quarter-warp fp16 SpMM body with depth-1 gather prefetch.
// Warp = 4 quarters x 8 lanes; each quarter owns a contiguous edge sub-chunk;
// each lane owns 8 dims (one LDG.128 of fp16 per edge per lane).
// Rows sorted -> register accumulation, vector-red flush on row change.
// NORM: multiply edge value by 1/(rowsum[row]+eps) (path softmax fold).
// ============================================================================
template<bool NORM>
__device__ __forceinline__ void spmm_chunk(
    const int* __restrict__ rows, const int* __restrict__ cols,
    const float* __restrict__ vals, const float* __restrict__ rowsum,
    int base, int cnt, float scale,
    const uint4* __restrict__ x, float* __restrict__ y,
    float4* __restrict__ meta, int lane)
{
    for (int i = lane; i < cnt; i += 32) {
        int gi = base + i;
        meta[i] = make_float4(__int_as_float(rows[gi]), __int_as_float(cols[gi]),
                              vals[gi] * scale, 0.f);
    }
    __syncwarp();
    const int ql   = lane & 7;
    const int qbeg = (lane >> 3) * QE;
    const int qend = min(qbeg + QE, cnt);
    if (qbeg >= qend) return;

    float acc[8];
    #pragma unroll
    for (int k = 0; k < 8; k++) acc[k] = 0.f;
    int cur = -1; float inv = 1.f;

    // prime prefetch
    float4 md = meta[qbeg];
    uint4  hv = x[(size_t)__float_as_int(md.y) * 8 + ql];

    for (int j = qbeg; j < qend; j++) {
        // prefetch next edge's gather before consuming this one
        float4 mdn = md; uint4 hvn = hv;
        if (j + 1 < qend) {
            mdn = meta[j + 1];
            hvn = x[(size_t)__float_as_int(mdn.y) * 8 + ql];
        }
        int rj = __float_as_int(md.x);
        if (rj != cur) {
            if (cur >= 0) flushv4(y, cur, ql, acc);
            cur = rj;
            #pragma unroll
            for (int k = 0; k < 8; k++) acc[k] = 0.f;
            if (NORM) inv = 1.f / (rowsum[rj] + 1e-12f);
        }
        float f = NORM ? md.z * inv : md.z;
        float2 p0 = __half22float2(*(const __half2*)&hv.x);
        float2 p1 = __half22float2(*(const __half2*)&hv.y);
        float2 p2 = __half22float2(*(const __half2*)&hv.z);
        float2 p3 = __half22float2(*(const __half2*)&hv.w);
        acc[0] = fmaf(f, p0.x, acc[0]); acc[1] = fmaf(f, p0.y, acc[1]);
        acc[2] = fmaf(f, p1.x, acc[2]); acc[3] = fmaf(f, p1.y, acc[3]);
        acc[4] = fmaf(f, p2.x, acc[4]); acc[5] = fmaf(f, p2.y, acc[5]);
        acc[6] = fmaf(f, p3.x, acc[6]); acc[7] = fmaf(f, p3.y, acc[7]);
        md = mdn; hv = hvn;
    }
    flushv4(y, cur, ql, acc);
}

// ---------------- fused pos+neg layer SpMM ----------------------------------
__global__ __launch_bounds__(256) void k_spmm_dual(
    const int* __restrict__ prow, const int* __restrict__ pcol,
    const float* __restrict__ pval, int npos, int pos_blocks,
    const int* __restrict__ nrow, const int* __restrict__ ncol,
    const float* __restrict__ nval, int nneg,
    const uint4* __restrict__ x, float* __restrict__ y)
{
    __shared__ float4 meta[8][WEDGES];
    const int wslot = threadIdx.x >> 5;
    const int lane  = threadIdx.x & 31;

    const bool isneg = (blockIdx.x >= pos_blocks);
    const int  bid   = isneg ? (blockIdx.x - pos_blocks) : blockIdx.x;
    const int* rows  = isneg ? nrow : prow;
    const int* cols  = isneg ? ncol : pcol;
    const float* vals = isneg ? nval : pval;
    const int  n     = isneg ? nneg : npos;
    const float scale = isneg ? -ALPHA : 1.0f;

    const int base = (bid * 8 + wslot) * WEDGES;
    if (base >= n) return;
    const int cnt = min(WEDGES, n - base);
    spmm_chunk<false>(rows, cols, vals, nullptr, base, cnt, scale, x, y,
                      meta[wslot], lane);
}

// ---------------- path SpMM (fp16 gather + fused softmax normalization) ----
__global__ __launch_bounds__(256) void k_spmm_path(
    const int* __restrict__ rows, const int* __restrict__ cols,
    const float* __restrict__ evals, const float* __restrict__ rowsum, int n,
    const uint4* __restrict__ x, float* __restrict__ y)
{
    __shared__ float4 meta[8][WEDGES];
    const int wslot = threadIdx.x >> 5;
    const int lane  = threadIdx.x & 31;
    const int base  = (blockIdx.x * 8 + wslot) * WEDGES;
    if (base >= n) return;
    const int cnt = min(WEDGES, n - base);
    spmm_chunk<true>(rows, cols, evals, rowsum, base, cnt, 1.0f, x, y,
                     meta[wslot], lane);
}

// ---------------- e0 epilogue: H0 = half(t); t = 0 ---------------------------
__global__ void k_init(float4* __restrict__ T, __half2* __restrict__ H, int n4)
{
    int i = blockIdx.x * blockDim.x + threadIdx.x;
    if (i >= n4) return;
    float4 t = T[i];
    H[2 * i]     = __floats2half2_rn(t.x, t.y);
    H[2 * i + 1] = __floats2half2_rn(t.z, t.w);
    T[i] = make_float4(0.f, 0.f, 0.f, 0.f);
}

// ---------------- layer epilogue: Hnew = half(t + a*Hold); t = 0 -------------
__global__ void k_layer(float4* __restrict__ T, const __half2* __restrict__ Hold,
                        __half2* __restrict__ Hnew, int n4)
{
    int i = blockIdx.x * blockDim.x + threadIdx.x;
    if (i >= n4) return;
    float4 t = T[i];
    float2 e01 = __half22float2(Hold[2 * i]);
    float2 e23 = __half22float2(Hold[2 * i + 1]);
    Hnew[2 * i]     = __floats2half2_rn(fmaf(ALPHA, e01.x, t.x), fmaf(ALPHA, e01.y, t.y));
    Hnew[2 * i + 1] = __floats2half2_rn(fmaf(ALPHA, e23.x, t.z), fmaf(ALPHA, e23.y, t.w));
    T[i] = make_float4(0.f, 0.f, 0.f, 0.f);
}

// ---------------- final: out = (H0 + H1 + H2 + (t + a*H2))/4; t = 0 ----------
__global__ void k_final(float4* __restrict__ T,
                        const __half2* __restrict__ H0,
                        const __half2* __restrict__ H1,
                        const __half2* __restrict__ H2,
                        float4* __restrict__ O, int n4)
{
    int i = blockIdx.x * blockDim.x + threadIdx.x;
    if (i >= n4) return;
    float4 t = T[i];
    float2 a01 = __half22float2(H0[2 * i]);
    float2 a23 = __half22float2(H0[2 * i + 1]);
    float2 b01 = __half22float2(H1[2 * i]);
    float2 b23 = __half22float2(H1[2 * i + 1]);
    float2 c01 = __half22float2(H2[2 * i]);
    float2 c23 = __half22float2(H2[2 * i + 1]);
    float4 o;
    o.x = (a01.x + b01.x + c01.x + fmaf(ALPHA, c01.x, t.x)) * 0.25f;
    o.y = (a01.y + b01.y + c01.y + fmaf(ALPHA, c01.y, t.y)) * 0.25f;
    o.z = (a23.x + b23.x + c23.x + fmaf(ALPHA, c23.x, t.z)) * 0.25f;
    o.w = (a23.y + b23.y + c23.y + fmaf(ALPHA, c23.y, t.w)) * 0.25f;
    O[i] = o;
    T[i] = make_float4(0.f, 0.f, 0.f, 0.f);   // keep zero-at-entry invariant
}

// ---------------------------------------------------------------------------
extern "C" void kernel_launch(void* const* d_in, const int* in_sizes, int n_in,
                              void* d_out, int out_size)
{
    const float* user_emb = (const float*)d_in[0];
    const float* item_emb = (const float*)d_in[1];
    const float* theta    = (const float*)d_in[2];
    const int*   pos_row  = (const int*)d_in[3];
    const int*   pos_col  = (const int*)d_in[4];
    const float* pos_val  = (const float*)d_in[5];
    const int*   neg_row  = (const int*)d_in[6];
    const int*   neg_col  = (const int*)d_in[7];
    const float* neg_val  = (const float*)d_in[8];
    const int*   p_row    = (const int*)d_in[9];
    const int*   p_col    = (const int*)d_in[10];
    const float* p_counts = (const float*)d_in[11];

    const int n_pos  = in_sizes[3];
    const int n_neg  = in_sizes[6];
    int n_path = in_sizes[9];
    if (n_path > MAX_EPATH) n_path = MAX_EPATH;
    const int n_theta = in_sizes[2] < 8 ? in_sizes[2] : 8;

    float *pt, *psv, *prs, *ptw;
    __half2 *hin, *h0, *h1, *h2;
    cudaGetSymbolAddress((void**)&pt,  g_t);
    cudaGetSymbolAddress((void**)&hin, g_hin);
    cudaGetSymbolAddress((void**)&h0,  g_h0);
    cudaGetSymbolAddress((void**)&h1,  g_h1);
    cudaGetSymbolAddress((void**)&h2,  g_h2);
    cudaGetSymbolAddress((void**)&psv, g_softv);
    cudaGetSymbolAddress((void**)&prs, g_rowsum);
    cudaGetSymbolAddress((void**)&ptw, g_thetaw);

    const int TB = 256;

    // theta softmax + rowsum zero + fp16 input table (independent)
    k_theta<<<1, 1>>>(theta, ptw, n_theta);
    k_zero4<<<(NUM_NODES / 4 + TB - 1) / TB, TB>>>((float4*)prs, NUM_NODES / 4);
    k_cvt<<<(NE4 + TB - 1) / TB, TB>>>((const float4*)user_emb,
                                       (const float4*)item_emb, hin, NE4);

    // path edge weights (exp + rowsums); normalization folded into spmm
    k_path1<<<(n_path + TB - 1) / TB, TB>>>(p_row, p_counts, ptw, psv, prs, n_path);

    // e0 = spmm(path, softv/rowsum, hin) -> t
    {
        int warps = (n_path + WEDGES - 1) / WEDGES;
        k_spmm_path<<<(warps + 7) / 8, TB>>>(p_row, p_col, psv, prs, n_path,
                                             (const uint4*)hin, pt);
    }

    // H0 = half(e0); t = 0
    k_init<<<(NE4 + TB - 1) / TB, TB>>>((float4*)pt, h0, NE4);

    const int pos_blocks = ((n_pos + WEDGES - 1) / WEDGES + 7) / 8;
    const int neg_blocks = ((n_neg + WEDGES - 1) / WEDGES + 7) / 8;
    const int dual_grid  = pos_blocks + neg_blocks;

    // layer 1
    k_spmm_dual<<<dual_grid, TB>>>(pos_row, pos_col, pos_val, n_pos, pos_blocks,
                                   neg_row, neg_col, neg_val, n_neg,
                                   (const uint4*)h0, pt);
    k_layer<<<(NE4 + TB - 1) / TB, TB>>>((float4*)pt, h0, h1, NE4);

    // layer 2
    k_spmm_dual<<<dual_grid, TB>>>(pos_row, pos_col, pos_val, n_pos, pos_blocks,
                                   neg_row, neg_col, neg_val, n_neg,
                                   (const uint4*)h1, pt);
    k_layer<<<(NE4 + TB - 1) / TB, TB>>>((float4*)pt, h1, h2, NE4);

    // layer 3 + fused final mean
    k_spmm_dual<<<dual_grid, TB>>>(pos_row, pos_col, pos_val, n_pos, pos_blocks,
                                   neg_row, neg_col, neg_val, n_neg,
                                   (const uint4*)h2, pt);
    k_final<<<(NE4 + TB - 1) / TB, TB>>>((float4*)pt, h0, h1, h2,
                                         (float4*)d_out, NE4);
}